// round 3
// baseline (speedup 1.0000x reference)
#include <cuda_runtime.h>
#include <cuda_fp16.h>
#include <cstdint>
#include <cstddef>

// ---------------- problem constants ----------------
#define B_   16
#define P_   512
#define MS_  13
#define D_   768
#define LH_  144
#define K_   9216
#define BP_  8192

// ---------------- GEMM tiling ----------------
#define BM   128
#define BN   128
#define BK   32
#define NKT  288

// smem strides (bytes); +16B pad => ldmatrix/LDS conflict-free
#define RAW_STRIDE 144        // 32 floats + pad
#define A16_STRIDE 144        // 64 halves + pad
#define W16_STRIDE 272        // 128 halves + pad
#define RAW_BYTES (BM * RAW_STRIDE)   // 18432
#define A16_BYTES (BM * A16_STRIDE)   // 18432
#define W16_BYTES (BK * W16_STRIDE)   // 8704
#define OFF_RAW  0
#define OFF_A16  (3 * RAW_BYTES)             // 55296
#define OFF_W16  (OFF_A16 + 2 * A16_BYTES)   // 92160
#define OFF_MASK (OFF_W16 + 4 * W16_BYTES)   // 126976
#define SMEM_BYTES (OFF_MASK + LH_ * 4)      // 127552

__device__ __half g_Wh[(size_t)K_ * D_];     // W_O as fp16, [K][D]
__device__ float  g_cbase[B_ * D_];

#define DEVI __device__ __forceinline__

DEVI uint32_t smem_u32(const void* p) {
    uint32_t a;
    asm("{ .reg .u64 t; cvta.to.shared.u64 t, %1; cvt.u32.u64 %0, t; }"
        : "=r"(a) : "l"(p));
    return a;
}
DEVI void cp16(uint32_t dst, const void* src) {
    asm volatile("cp.async.cg.shared.global [%0], [%1], 16;" :: "r"(dst), "l"(src));
}
DEVI void cp_commit() { asm volatile("cp.async.commit_group;" ::: "memory"); }

DEVI uint32_t packh(float lo, float hi) {     // half2: [15:0]=lo, [31:16]=hi
    uint32_t r;
    asm("cvt.rn.f16x2.f32 %0, %1, %2;" : "=r"(r) : "f"(hi), "f"(lo));
    return r;
}
DEVI void sts128(uint32_t addr, uint32_t a, uint32_t b, uint32_t c, uint32_t d) {
    asm volatile("st.shared.v4.b32 [%0], {%1, %2, %3, %4};"
                 :: "r"(addr), "r"(a), "r"(b), "r"(c), "r"(d) : "memory");
}
DEVI void ldsm4(uint32_t* r, uint32_t addr) {
    asm volatile("ldmatrix.sync.aligned.m8n8.x4.shared.b16 {%0,%1,%2,%3}, [%4];"
                 : "=r"(r[0]), "=r"(r[1]), "=r"(r[2]), "=r"(r[3]) : "r"(addr));
}
DEVI void ldsm4t(uint32_t* r, uint32_t addr) {
    asm volatile("ldmatrix.sync.aligned.m8n8.x4.trans.shared.b16 {%0,%1,%2,%3}, [%4];"
                 : "=r"(r[0]), "=r"(r[1]), "=r"(r[2]), "=r"(r[3]) : "r"(addr));
}
DEVI void mma16(float* d, const uint32_t* a, const uint32_t* b) {
    asm volatile(
        "mma.sync.aligned.m16n8k16.row.col.f32.f16.f16.f32 "
        "{%0,%1,%2,%3},{%4,%5,%6,%7},{%8,%9},{%0,%1,%2,%3};"
        : "+f"(d[0]), "+f"(d[1]), "+f"(d[2]), "+f"(d[3])
        : "r"(a[0]), "r"(a[1]), "r"(a[2]), "r"(a[3]), "r"(b[0]), "r"(b[1]));
}

// ---------------- prep: W -> fp16 ----------------
__global__ void __launch_bounds__(256) wcvt_kernel(const float* __restrict__ W) {
    const int i = blockIdx.x * 256 + threadIdx.x;     // over K_*D_/4
    const float4 v = ((const float4*)W)[i];
    uint2 h;
    h.x = packh(v.x, v.y);
    h.y = packh(v.z, v.w);
    ((uint2*)g_Wh)[i] = h;
}

// ---------------- prep: per-(b,d) constant term ----------------
__global__ void cbase_kernel(const float* __restrict__ mlp_mask,
                             const float* __restrict__ attn_mask,
                             const float* __restrict__ mlp_const,
                             const float* __restrict__ attn_const,
                             const float* __restrict__ post_bias) {
    const int i = blockIdx.x * blockDim.x + threadIdx.x;
    if (i >= B_ * D_) return;
    const int b = i / D_, d = i % D_;
    float a0 = post_bias[d], a1 = 0.f, a2 = 0.f, a3 = 0.f;
#pragma unroll
    for (int m = 0; m < MS_; m++)
        a0 += (1.0f - mlp_mask[b * MS_ + m]) * mlp_const[m * D_ + d];
#pragma unroll 4
    for (int lh = 0; lh < LH_; lh += 4) {
        a0 += (1.0f - attn_mask[b * LH_ + lh + 0]) * attn_const[(lh + 0) * D_ + d];
        a1 += (1.0f - attn_mask[b * LH_ + lh + 1]) * attn_const[(lh + 1) * D_ + d];
        a2 += (1.0f - attn_mask[b * LH_ + lh + 2]) * attn_const[(lh + 2) * D_ + d];
        a3 += (1.0f - attn_mask[b * LH_ + lh + 3]) * attn_const[(lh + 3) * D_ + d];
    }
    g_cbase[i] = (a0 + a1) + (a2 + a3);
}

// ---------------- mlp term + constants -> out ----------------
__global__ void __launch_bounds__(256)
mlp_kernel(const float* __restrict__ mlp_cache,
           const float* __restrict__ mlp_mask,
           float* __restrict__ out) {
    const int idx = blockIdx.x * blockDim.x + threadIdx.x;   // over BP*D/4
    if (idx >= BP_ * D_ / 4) return;
    const int e = idx * 4;
    const int bp = e / D_;
    const int d = e % D_;
    const int b = bp >> 9;
    const float* src = mlp_cache + (size_t)bp * MS_ * D_ + d;
    const float* mmk = mlp_mask + b * MS_;
    float4 acc = *(const float4*)(&g_cbase[b * D_ + d]);
#pragma unroll
    for (int m = 0; m < MS_; m++) {
        const float s = __ldg(mmk + m);
        const float4 v = *(const float4*)(src + (size_t)m * D_);
        acc.x += s * v.x; acc.y += s * v.y; acc.z += s * v.z; acc.w += s * v.w;
    }
    *(float4*)(out + e) = acc;
}

// ---------------- GEMM helpers ----------------
DEVI void issue_cp(uint32_t smb, const float* Abase, const __half* Wbase,
                   int kt, int tid) {
    const uint32_t ra = smb + OFF_RAW + (uint32_t)(kt % 3) * RAW_BYTES;
    const float* ag = Abase + (size_t)kt * BK;
    const int c = tid & 7, r0 = tid >> 3;
#pragma unroll
    for (int i = 0; i < 4; i++) {
        const int r = r0 + i * 32;
        cp16(ra + (uint32_t)(r * RAW_STRIDE + c * 16), ag + (size_t)r * K_ + c * 4);
    }
    const uint32_t ws = smb + OFF_W16 + (uint32_t)(kt & 3) * W16_BYTES;
    const __half* wg = Wbase + (size_t)kt * BK * D_;
    const int gc = tid & 15, wr = tid >> 4;
#pragma unroll
    for (int i = 0; i < 2; i++) {
        const int r = wr + i * 16;
        cp16(ws + (uint32_t)(r * W16_STRIDE + gc * 16), wg + (size_t)r * D_ + gc * 8);
    }
    cp_commit();
}

DEVI void convert_a(char* smem, uint32_t smb, const float* smask, int kt1, int tid) {
    const float s = smask[kt1 >> 1];          // one (l,h) mask per 64-k block
    const float4* src = (const float4*)(smem + OFF_RAW + (kt1 % 3) * RAW_BYTES
                                        + tid * RAW_STRIDE);
    const uint32_t dst = smb + OFF_A16 + (uint32_t)(kt1 & 1) * A16_BYTES
                         + (uint32_t)tid * A16_STRIDE;
#pragma unroll
    for (int i = 0; i < 4; i++) {
        const float4 x = src[2 * i], y = src[2 * i + 1];
        sts128(dst + i * 16,
               packh(x.x * s, x.y * s), packh(x.z * s, x.w * s),
               packh(y.x * s, y.y * s), packh(y.z * s, y.w * s));
    }
}

// ---------------- GEMM: out += (mask*A) @ W (fp16 mma, warp-specialized) ----
__global__ void __launch_bounds__(256, 1)
gemm_kernel(const float* __restrict__ A,
            const float* __restrict__ attn_mask,
            float* __restrict__ out) {
    extern __shared__ char smem[];
    const uint32_t smb = smem_u32(smem);
    const int tid = threadIdx.x;
    const int wid = tid >> 5, lane = tid & 31;
    const int ntile = blockIdx.x, mtile = blockIdx.y;
    const int b = mtile >> 2;
    const int row0 = mtile * BM, n0 = ntile * BN;
    const float* Abase = A + (size_t)row0 * K_;
    const __half* Wbase = g_Wh + n0;
    float* smask = (float*)(smem + OFF_MASK);

    if (tid < LH_) smask[tid] = attn_mask[b * LH_ + tid];

    issue_cp(smb, Abase, Wbase, 0, tid);
    issue_cp(smb, Abase, Wbase, 1, tid);
    issue_cp(smb, Abase, Wbase, 2, tid);
    asm volatile("cp.async.wait_group 2;" ::: "memory");
    __syncthreads();
    if (tid < 128) convert_a(smem, smb, smask, 0, tid);

    // consumer state
    const int cw = wid - 4;
    const int wm = (cw & 1) * 64, wn = (cw >> 1) * 64;
    float acc[4][8][4];
#pragma unroll
    for (int i = 0; i < 4; i++)
#pragma unroll
        for (int j = 0; j < 8; j++)
#pragma unroll
            for (int k = 0; k < 4; k++) acc[i][j][k] = 0.0f;

    for (int kt = 0; kt < NKT; ++kt) {
        asm volatile("cp.async.wait_group 1;" ::: "memory");
        __syncthreads();
        if (kt + 3 < NKT) issue_cp(smb, Abase, Wbase, kt + 3, tid);

        if (tid < 128) {
            if (kt + 1 < NKT) convert_a(smem, smb, smask, kt + 1, tid);
        } else {
            const uint32_t a16 = smb + OFF_A16 + (uint32_t)(kt & 1) * A16_BYTES;
            const uint32_t ws = smb + OFF_W16 + (uint32_t)(kt & 3) * W16_BYTES;
#pragma unroll
            for (int ks = 0; ks < 2; ks++) {
                uint32_t af[4][4];
#pragma unroll
                for (int im = 0; im < 4; im++)
                    ldsm4(af[im], a16 + (uint32_t)((wm + im * 16 + (lane & 15)) * A16_STRIDE
                                                   + ks * 32 + (lane >> 4) * 16));
                uint32_t bf[8][2];
#pragma unroll
                for (int n2 = 0; n2 < 4; n2++) {
                    uint32_t t[4];
                    ldsm4t(t, ws + (uint32_t)((ks * 16 + (lane & 15)) * W16_STRIDE
                                              + (wn + n2 * 16 + (lane >> 4) * 8) * 2));
                    bf[2 * n2][0] = t[0]; bf[2 * n2][1] = t[1];
                    bf[2 * n2 + 1][0] = t[2]; bf[2 * n2 + 1][1] = t[3];
                }
#pragma unroll
                for (int im = 0; im < 4; im++)
#pragma unroll
                    for (int nb = 0; nb < 8; nb++)
                        mma16(acc[im][nb], af[im], bf[nb]);
            }
        }
    }

    // epilogue: RMW add onto out (mlp kernel wrote the base)
    if (tid >= 128) {
        const int r0g = row0 + wm + (lane >> 2);
        const int c0g = n0 + wn + (lane & 3) * 2;
#pragma unroll
        for (int im = 0; im < 4; im++) {
            const int r = r0g + im * 16;
#pragma unroll
            for (int nb = 0; nb < 8; nb++) {
                const int c = c0g + nb * 8;
                float2* p0 = (float2*)(out + (size_t)r * D_ + c);
                float2* p1 = (float2*)(out + (size_t)(r + 8) * D_ + c);
                float2 v0 = *p0, v1 = *p1;
                v0.x += acc[im][nb][0]; v0.y += acc[im][nb][1];
                v1.x += acc[im][nb][2]; v1.y += acc[im][nb][3];
                *p0 = v0; *p1 = v1;
            }
        }
    }
}

// ---------------- launch ----------------
extern "C" void kernel_launch(void* const* d_in, const int* in_sizes, int n_in,
                              void* d_out, int out_size) {
    const float* mlp_cache  = (const float*)d_in[0];
    const float* attn_cache = (const float*)d_in[1];
    const float* mlp_mask   = (const float*)d_in[2];
    const float* attn_mask  = (const float*)d_in[3];
    const float* mlp_const  = (const float*)d_in[4];
    const float* attn_const = (const float*)d_in[5];
    const float* W_O        = (const float*)d_in[6];
    const float* post_bias  = (const float*)d_in[7];
    float* out = (float*)d_out;

    cudaFuncSetAttribute(gemm_kernel, cudaFuncAttributeMaxDynamicSharedMemorySize, SMEM_BYTES);

    wcvt_kernel<<<K_ * D_ / 4 / 256, 256>>>(W_O);
    cbase_kernel<<<(B_ * D_ + 255) / 256, 256>>>(mlp_mask, attn_mask, mlp_const,
                                                 attn_const, post_bias);
    mlp_kernel<<<(BP_ * D_ / 4 + 255) / 256, 256>>>(mlp_cache, mlp_mask, out);
    gemm_kernel<<<dim3(D_ / BN, BP_ / BM), 256, SMEM_BYTES>>>(attn_cache, attn_mask, out);
}

// round 4
// speedup vs baseline: 1.0375x; 1.0375x over previous
#include <cuda_runtime.h>
#include <cuda_fp16.h>
#include <cstdint>
#include <cstddef>

// ---------------- problem constants ----------------
#define B_   16
#define P_   512
#define MS_  13
#define D_   768
#define LH_  144
#define K_   9216
#define BP_  8192

// ---------------- GEMM tiling ----------------
#define BM   128
#define BN   128
#define BK   64          // == DH: one (l,h) mask scalar per k-tile
#define NKT  144
#define NTHREADS 512

// smem layout (bytes)
#define A16_STRIDE 144                 // 64 halves (128B) + 16B pad
#define W16_STRIDE 272                 // 128 halves (256B) + 16B pad
#define A16_BYTES (BM * A16_STRIDE)    // 18432, 2 stages
#define W16_BYTES (BK * W16_STRIDE)    // 17408, 4 stages
#define OFF_A16  0
#define OFF_W16  (2 * A16_BYTES)               // 36864
#define OFF_MASK (OFF_W16 + 4 * W16_BYTES)     // 106496
#define SMEM_BYTES (OFF_MASK + NKT * 4)        // 107072

__device__ __half g_Wh[(size_t)K_ * D_];
__device__ float  g_cbase[B_ * D_];

#define DEVI __device__ __forceinline__

DEVI uint32_t smem_u32(const void* p) {
    uint32_t a;
    asm("{ .reg .u64 t; cvta.to.shared.u64 t, %1; cvt.u32.u64 %0, t; }"
        : "=r"(a) : "l"(p));
    return a;
}
DEVI void cp16(uint32_t dst, const void* src) {
    asm volatile("cp.async.cg.shared.global [%0], [%1], 16;" :: "r"(dst), "l"(src));
}
DEVI void cp_commit() { asm volatile("cp.async.commit_group;" ::: "memory"); }
DEVI void cp_wait2()  { asm volatile("cp.async.wait_group 2;" ::: "memory"); }

DEVI uint32_t packh(float lo, float hi) {   // half2: [15:0]=lo, [31:16]=hi
    uint32_t r;
    asm("cvt.rn.f16x2.f32 %0, %1, %2;" : "=r"(r) : "f"(hi), "f"(lo));
    return r;
}
DEVI void sts128(uint32_t addr, uint32_t a, uint32_t b, uint32_t c, uint32_t d) {
    asm volatile("st.shared.v4.b32 [%0], {%1, %2, %3, %4};"
                 :: "r"(addr), "r"(a), "r"(b), "r"(c), "r"(d) : "memory");
}
DEVI void ldsm4(uint32_t* r, uint32_t addr) {
    asm volatile("ldmatrix.sync.aligned.m8n8.x4.shared.b16 {%0,%1,%2,%3}, [%4];"
                 : "=r"(r[0]), "=r"(r[1]), "=r"(r[2]), "=r"(r[3]) : "r"(addr));
}
DEVI void ldsm4t(uint32_t* r, uint32_t addr) {
    asm volatile("ldmatrix.sync.aligned.m8n8.x4.trans.shared.b16 {%0,%1,%2,%3}, [%4];"
                 : "=r"(r[0]), "=r"(r[1]), "=r"(r[2]), "=r"(r[3]) : "r"(addr));
}
DEVI void mma16(float* d, const uint32_t* a, const uint32_t* b) {
    asm volatile(
        "mma.sync.aligned.m16n8k16.row.col.f32.f16.f16.f32 "
        "{%0,%1,%2,%3},{%4,%5,%6,%7},{%8,%9},{%0,%1,%2,%3};"
        : "+f"(d[0]), "+f"(d[1]), "+f"(d[2]), "+f"(d[3])
        : "r"(a[0]), "r"(a[1]), "r"(a[2]), "r"(a[3]), "r"(b[0]), "r"(b[1]));
}

// ---------------- prep: W -> fp16 ----------------
__global__ void __launch_bounds__(256) wcvt_kernel(const float* __restrict__ W) {
    const int i = blockIdx.x * 256 + threadIdx.x;
    const float4 v = ((const float4*)W)[i];
    uint2 h;
    h.x = packh(v.x, v.y);
    h.y = packh(v.z, v.w);
    ((uint2*)g_Wh)[i] = h;
}

// ---------------- prep: per-(b,d) constant term (lh-parallel + reduce) -----
__global__ void __launch_bounds__(256)
cbase_kernel(const float* __restrict__ mlp_mask,
             const float* __restrict__ attn_mask,
             const float* __restrict__ mlp_const,
             const float* __restrict__ attn_const,
             const float* __restrict__ post_bias) {
    __shared__ float red[4][64];
    const int tid = threadIdx.x;
    const int dl = tid & 63, g = tid >> 6;          // 4 lh-groups of 36
    const int d = blockIdx.x * 64 + dl;
    const int b = blockIdx.y;
    float acc = 0.f;
#pragma unroll 4
    for (int lh = g * 36; lh < (g + 1) * 36; lh++)
        acc += (1.0f - attn_mask[b * LH_ + lh]) * attn_const[lh * D_ + d];
    if (g == 0) {
        acc += post_bias[d];
#pragma unroll
        for (int m = 0; m < MS_; m++)
            acc += (1.0f - mlp_mask[b * MS_ + m]) * mlp_const[m * D_ + d];
    }
    red[g][dl] = acc;
    __syncthreads();
    if (g == 0)
        g_cbase[b * D_ + d] = (red[0][dl] + red[1][dl]) + (red[2][dl] + red[3][dl]);
}

// ---------------- mlp term + constants -> out ----------------
__global__ void __launch_bounds__(256)
mlp_kernel(const float* __restrict__ mlp_cache,
           const float* __restrict__ mlp_mask,
           float* __restrict__ out) {
    const int idx = blockIdx.x * blockDim.x + threadIdx.x;   // over BP*D/4
    if (idx >= BP_ * D_ / 4) return;
    const int e = idx * 4;
    const int bp = e / D_;
    const int d = e % D_;
    const int b = bp >> 9;
    const float* src = mlp_cache + (size_t)bp * MS_ * D_ + d;
    const float* mmk = mlp_mask + b * MS_;
    float4 acc = *(const float4*)(&g_cbase[b * D_ + d]);
#pragma unroll
    for (int m = 0; m < MS_; m++) {
        const float s = __ldg(mmk + m);
        const float4 v = *(const float4*)(src + (size_t)m * D_);
        acc.x += s * v.x; acc.y += s * v.y; acc.z += s * v.z; acc.w += s * v.w;
    }
    *(float4*)(out + e) = acc;
}

// ---------------- GEMM ----------------
DEVI void ldgA(float4* st, const float* Abase, int kt, int row, int colb) {
#pragma unroll
    for (int i = 0; i < 4; i++)
        st[i] = *(const float4*)(Abase + (size_t)row * K_ + kt * BK + colb + i * 4);
}

DEVI void cvtA(const float4* st, float s, uint32_t dst) {
    // dst = a16 base + row*A16_STRIDE + colb*2 (bytes)
    const float4 x0 = st[0], x1 = st[1], x2 = st[2], x3 = st[3];
    sts128(dst,
           packh(x0.x * s, x0.y * s), packh(x0.z * s, x0.w * s),
           packh(x1.x * s, x1.y * s), packh(x1.z * s, x1.w * s));
    sts128(dst + 16,
           packh(x2.x * s, x2.y * s), packh(x2.z * s, x2.w * s),
           packh(x3.x * s, x3.y * s), packh(x3.z * s, x3.w * s));
}

DEVI void cpW(uint32_t ws, const __half* Wbase, int kt, int tid) {
    const int r0 = tid >> 4, c = tid & 15;
    const __half* wg = Wbase + (size_t)kt * BK * D_;
#pragma unroll
    for (int i = 0; i < 2; i++) {
        const int r = r0 + i * 32;
        cp16(ws + (uint32_t)(r * W16_STRIDE + c * 16), wg + (size_t)r * D_ + c * 8);
    }
}

__global__ void __launch_bounds__(NTHREADS, 1)
gemm_kernel(const float* __restrict__ A,
            const float* __restrict__ attn_mask,
            float* __restrict__ out) {
    extern __shared__ char smem[];
    const uint32_t smb = smem_u32(smem);
    const int tid = threadIdx.x;
    const int wid = tid >> 5, lane = tid & 31;
    const int ntile = blockIdx.x, mtile = blockIdx.y;
    const int b = mtile >> 2;
    const int row0 = mtile * BM, n0 = ntile * BN;
    const float* Abase = A + (size_t)row0 * K_;
    const __half* Wbase = g_Wh + n0;
    float* smask = (float*)(smem + OFF_MASK);

    const int wm = (wid & 3) * 32, wn = (wid >> 2) * 32;
    const int arow = tid >> 2, acolb = (tid & 3) * 16;      // A ldg/sts coords
    const uint32_t a16st = (uint32_t)(arow * A16_STRIDE + acolb * 2);

    if (tid < NKT) smask[tid] = attn_mask[b * LH_ + tid];

    // prologue: W stages 0..2, A regs for kt 0,1; convert kt0
    cpW(smb + OFF_W16 + 0 * W16_BYTES, Wbase, 0, tid); cp_commit();
    cpW(smb + OFF_W16 + 1 * W16_BYTES, Wbase, 1, tid); cp_commit();
    cpW(smb + OFF_W16 + 2 * W16_BYTES, Wbase, 2, tid); cp_commit();
    float4 st[2][4];
    ldgA(st[0], Abase, 0, arow, acolb);
    ldgA(st[1], Abase, 1, arow, acolb);
    __syncthreads();                       // smask visible
    cvtA(st[0], smask[0], smb + OFF_A16 + a16st);

    float acc[2][4][4];
#pragma unroll
    for (int i = 0; i < 2; i++)
#pragma unroll
        for (int j = 0; j < 4; j++)
#pragma unroll
            for (int k = 0; k < 4; k++) acc[i][j][k] = 0.0f;

    for (int kt = 0; kt < NKT; ++kt) {
        cp_wait2();
        __syncthreads();                   // W(kt) + a16[kt&1] visible everywhere

        if (kt + 2 < NKT) ldgA(st[kt & 1], Abase, kt + 2, arow, acolb);
        if (kt + 3 < NKT) cpW(smb + OFF_W16 + (uint32_t)((kt + 3) & 3) * W16_BYTES,
                              Wbase, kt + 3, tid);
        cp_commit();
        if (kt + 1 < NKT)
            cvtA(st[(kt + 1) & 1], smask[kt + 1],
                 smb + OFF_A16 + (uint32_t)((kt + 1) & 1) * A16_BYTES + a16st);

        const uint32_t a16 = smb + OFF_A16 + (uint32_t)(kt & 1) * A16_BYTES;
        const uint32_t ws  = smb + OFF_W16 + (uint32_t)(kt & 3) * W16_BYTES;
#pragma unroll
        for (int ks = 0; ks < 4; ks++) {
            uint32_t af[2][4];
#pragma unroll
            for (int im = 0; im < 2; im++)
                ldsm4(af[im], a16 + (uint32_t)((wm + im * 16 + (lane & 15)) * A16_STRIDE
                                               + ks * 32 + (lane >> 4) * 16));
            uint32_t bf[4][2];
#pragma unroll
            for (int n2 = 0; n2 < 2; n2++) {
                uint32_t t[4];
                ldsm4t(t, ws + (uint32_t)((ks * 16 + (lane & 15)) * W16_STRIDE
                                          + (wn + n2 * 16 + (lane >> 4) * 8) * 2));
                bf[2 * n2][0] = t[0]; bf[2 * n2][1] = t[1];
                bf[2 * n2 + 1][0] = t[2]; bf[2 * n2 + 1][1] = t[3];
            }
#pragma unroll
            for (int im = 0; im < 2; im++)
#pragma unroll
                for (int nb = 0; nb < 4; nb++)
                    mma16(acc[im][nb], af[im], bf[nb]);
        }
    }

    // epilogue: RMW add onto out (mlp kernel wrote the base)
    const int r0g = row0 + wm + (lane >> 2);
    const int c0g = n0 + wn + (lane & 3) * 2;
#pragma unroll
    for (int im = 0; im < 2; im++) {
        const int r = r0g + im * 16;
#pragma unroll
        for (int nb = 0; nb < 4; nb++) {
            const int c = c0g + nb * 8;
            float2* p0 = (float2*)(out + (size_t)r * D_ + c);
            float2* p1 = (float2*)(out + (size_t)(r + 8) * D_ + c);
            float2 v0 = *p0, v1 = *p1;
            v0.x += acc[im][nb][0]; v0.y += acc[im][nb][1];
            v1.x += acc[im][nb][2]; v1.y += acc[im][nb][3];
            *p0 = v0; *p1 = v1;
        }
    }
}

// ---------------- launch ----------------
extern "C" void kernel_launch(void* const* d_in, const int* in_sizes, int n_in,
                              void* d_out, int out_size) {
    const float* mlp_cache  = (const float*)d_in[0];
    const float* attn_cache = (const float*)d_in[1];
    const float* mlp_mask   = (const float*)d_in[2];
    const float* attn_mask  = (const float*)d_in[3];
    const float* mlp_const  = (const float*)d_in[4];
    const float* attn_const = (const float*)d_in[5];
    const float* W_O        = (const float*)d_in[6];
    const float* post_bias  = (const float*)d_in[7];
    float* out = (float*)d_out;

    cudaFuncSetAttribute(gemm_kernel, cudaFuncAttributeMaxDynamicSharedMemorySize, SMEM_BYTES);

    wcvt_kernel<<<K_ * D_ / 4 / 256, 256>>>(W_O);
    cbase_kernel<<<dim3(D_ / 64, B_), 256>>>(mlp_mask, attn_mask, mlp_const,
                                             attn_const, post_bias);
    mlp_kernel<<<(BP_ * D_ / 4 + 255) / 256, 256>>>(mlp_cache, mlp_mask, out);
    gemm_kernel<<<dim3(D_ / BN, BP_ / BM), NTHREADS, SMEM_BYTES>>>(attn_cache,
                                                                   attn_mask, out);
}